// round 10
// baseline (speedup 1.0000x reference)
#include <cuda_runtime.h>
#include <cstdint>
#include <cstddef>

// f = H @ x + damp * x per molecule.
// hess: [M*96, 96] f32 row-major, ns: flat [M*96] f32, out: flat [M*96] f32.
// Three warps per CTA, each an INDEPENDENT 2-stage TMA pipeline over its own
// 32-row third of H (no cross-warp data sharing -> no __syncthreads in loop).
#define D 96
#define D4 24                      // D/4 vec4 columns
#define DD (D * D)
#define ROWS_W 32                  // rows per warp-tile
#define HW_BYTES (ROWS_W * D * 4)  // 12288 per warp third
#define H_BYTES  (DD * 4)          // 36864
#define X_BYTES  (D * 4)           // 384
#define NBLOCKS  456               // 152 SMs * 3 CTAs/SM

// dynamic smem layout:
//   [0, 2*H_BYTES)     : H stages (2 x 36864), thirds contiguous per stage
//   [+, 2*3*X_BYTES)   : x copies [stage][warp]
//   [+, 6*8)           : mbarriers [stage][warp]
#define SMEM_X_OFF    (2 * H_BYTES)
#define SMEM_MBAR_OFF (SMEM_X_OFF + 6 * X_BYTES)
#define SMEM_TOTAL    (SMEM_MBAR_OFF + 6 * 8)

__device__ __constant__ float kDampF = (float)(0.1 * 627.5094740631 /
                                               (0.529177210903 * 0.529177210903));

__device__ __forceinline__ uint32_t s2u(const void* p) {
    uint32_t a;
    asm("{ .reg .u64 t; cvta.to.shared.u64 t, %1; cvt.u32.u64 %0, t; }"
        : "=r"(a) : "l"(p));
    return a;
}

__device__ __forceinline__ void mbar_init(uint32_t mbar, uint32_t count) {
    asm volatile("mbarrier.init.shared.b64 [%0], %1;" :: "r"(mbar), "r"(count) : "memory");
}

__device__ __forceinline__ void mbar_expect_tx(uint32_t mbar, uint32_t bytes) {
    asm volatile("mbarrier.arrive.expect_tx.shared.b64 _, [%0], %1;"
                 :: "r"(mbar), "r"(bytes) : "memory");
}

__device__ __forceinline__ void mbar_wait(uint32_t mbar, uint32_t parity) {
    asm volatile(
        "{\n\t"
        ".reg .pred P;\n\t"
        "WAIT_%=:\n\t"
        "mbarrier.try_wait.parity.shared.b64 P, [%0], %1;\n\t"
        "@!P bra WAIT_%=;\n\t"
        "}"
        :: "r"(mbar), "r"(parity) : "memory");
}

__device__ __forceinline__ void bulk_g2s_ef(uint32_t dst_smem, const void* src_gmem,
                                            uint32_t bytes, uint32_t mbar) {
    asm volatile(
        "{\n\t"
        ".reg .b64 pol;\n\t"
        "createpolicy.fractional.L2::evict_first.b64 pol, 1.0;\n\t"
        "cp.async.bulk.shared::cluster.global.mbarrier::complete_tx::bytes.L2::cache_hint "
        "[%0], [%1], %2, [%3], pol;\n\t"
        "}"
        :: "r"(dst_smem), "l"(src_gmem), "r"(bytes), "r"(mbar) : "memory");
}

extern __shared__ char smem_raw[];

__global__ void __launch_bounds__(D, 3)
force_agg_kernel(const float* __restrict__ ns,
                 const float* __restrict__ hess,
                 float* __restrict__ out, int M) {
    float* Hs = reinterpret_cast<float*>(smem_raw);                 // [2][DD]
    float* xs = reinterpret_cast<float*>(smem_raw + SMEM_X_OFF);    // [2][3][D]
    const uint32_t mbar_base = s2u(smem_raw + SMEM_MBAR_OFF);       // [2][3]

    const int t = threadIdx.x;     // 0..95
    const int b = blockIdx.x;
    const int w = t >> 5;          // my warp = my third
    const int lane = t & 31;

    if (t < 6) mbar_init(mbar_base + 8u * t, 1);
    __syncthreads();               // only sync in the kernel: mbar init visibility

    const int stride = gridDim.x;
    const int cnt = (M - b + stride - 1) / stride;

    const uint32_t Hs_u = s2u(Hs);
    const uint32_t xs_u = s2u(xs);

    // my warp's smem slots (stage 0 / stage 1)
    const uint32_t my_h0 = Hs_u + (uint32_t)w * HW_BYTES;
    const uint32_t my_h1 = my_h0 + H_BYTES;
    const uint32_t my_x0 = xs_u + (uint32_t)w * X_BYTES;
    const uint32_t my_x1 = my_x0 + 3u * X_BYTES;
    const uint32_t my_mb0 = mbar_base + (uint32_t)w * 8u;
    const uint32_t my_mb1 = my_mb0 + 3u * 8u;

    const size_t mstepH = (size_t)stride * DD;
    const size_t mstepX = (size_t)stride * D;
    // gmem source for my warp's third of molecule k
    const float* hsrc = hess + (size_t)b * DD + w * (ROWS_W * D);
    const float* xsrc = ns + (size_t)b * D;
    float* out_p = out + (size_t)b * D + t;

    // prologue: my warp's fetches for k=0 (stage0) and k=1 (stage1)
    if (lane == 0) {
        mbar_expect_tx(my_mb0, HW_BYTES + X_BYTES);
        bulk_g2s_ef(my_h0, hsrc, HW_BYTES, my_mb0);
        bulk_g2s_ef(my_x0, xsrc, X_BYTES, my_mb0);
        if (cnt > 1) {
            mbar_expect_tx(my_mb1, HW_BYTES + X_BYTES);
            bulk_g2s_ef(my_h1, hsrc + mstepH, HW_BYTES, my_mb1);
            bulk_g2s_ef(my_x1, xsrc + mstepX, X_BYTES, my_mb1);
        }
    }
    const float* hess_next = hsrc + 2 * mstepH;   // molecule k+2 source
    const float* ns_next   = xsrc + 2 * mstepX;

    const int c0 = t % D4;         // rotated vec4-column start (conflict-free)
    // my row within my third is (t & 31) + nothing: thread t computes global row t,
    // which lives in my warp's third at local row (t - 32w) = lane.
    const float4* const Hrow_s0 =
        reinterpret_cast<const float4*>(Hs + (size_t)w * (ROWS_W * D) + (size_t)lane * D);
    const float4* const Hrow_s1 =
        reinterpret_cast<const float4*>(Hs + DD + (size_t)w * (ROWS_W * D) + (size_t)lane * D);
    const float* const xv_s0 = xs + w * D;
    const float* const xv_s1 = xs + (3 + w) * D;

    for (int k = 0; k < cnt; ++k) {
        const int s = k & 1;
        const uint32_t my_mb = s ? my_mb1 : my_mb0;

        // wait for my third of stage s (parity flips each stage reuse)
        mbar_wait(my_mb, (uint32_t)((k >> 1) & 1));

        const float4* __restrict__ Hrow4 = s ? Hrow_s1 : Hrow_s0;
        const float* __restrict__ xvec   = s ? xv_s1 : xv_s0;
        const float4* __restrict__ xv4   = reinterpret_cast<const float4*>(xvec);

        float a0 = 0.f, a1 = 0.f, a2 = 0.f, a3 = 0.f;
        int c = c0;
        #pragma unroll
        for (int it = 0; it < D4; ++it) {
            float4 h = Hrow4[c];
            float4 xv = xv4[c];
            a0 = fmaf(h.x, xv.x, a0);
            a1 = fmaf(h.y, xv.y, a1);
            a2 = fmaf(h.z, xv.z, a2);
            a3 = fmaf(h.w, xv.w, a3);
            ++c;
            if (c == D4) c = 0;
        }
        const float acc = fmaf(kDampF, xvec[t], (a0 + a1) + (a2 + a3));

        *out_p = acc;              // all LDS results consumed -> stage s readable done
        out_p += mstepX;

        // refill stage s with molecule k+2 (warp-private; no CTA sync needed).
        // acc depends on every load from stage s, so issuing here is safe.
        if (lane == 0 && (k + 2) < cnt) {
            mbar_expect_tx(my_mb, HW_BYTES + X_BYTES);
            bulk_g2s_ef(s ? my_h1 : my_h0, hess_next, HW_BYTES, my_mb);
            bulk_g2s_ef(s ? my_x1 : my_x0, ns_next, X_BYTES, my_mb);
        }
        hess_next += mstepH;
        ns_next   += mstepX;
    }
}

extern "C" void kernel_launch(void* const* d_in, const int* in_sizes, int n_in,
                              void* d_out, int out_size) {
    const float* ns   = (const float*)d_in[0];   // [N_tot,3] -> flat [M*96]
    const float* hess = (const float*)d_in[1];   // [M*96, 96]
    float* out = (float*)d_out;

    const int M = in_sizes[1] / DD;              // 8192

    cudaFuncSetAttribute(force_agg_kernel,
                         cudaFuncAttributeMaxDynamicSharedMemorySize, SMEM_TOTAL);
    force_agg_kernel<<<NBLOCKS, D, SMEM_TOTAL>>>(ns, hess, out, M);
}